// round 3
// baseline (speedup 1.0000x reference)
#include <cuda_runtime.h>

// GLoss fused single-kernel: g_loss + p_loss + g_d_loss.
//   d  = output - target            -> mean over 8 dirs of grad(d)^2, + mean d^2
//   dd = maxpool2(o) - maxpool2(t)  -> mean over 8 dirs of grad(dd)^2
//
// 64x64 full-res tile per 256-thread block, halo 2 (x-halo widened to 4 for
// float4 alignment). Per-block weighted partial -> g_part[bid]; the LAST block
// to arrive (threadfence-reduction pattern) sums all partials and writes out.

#define IMG   1024
#define HIMG  512
#define NIMG  8
#define TILE  64
#define GRIDX (IMG / TILE)           // 16
#define NBLK  (GRIDX * GRIDX * NIMG) // 2048

#define QX    18      // float4 units per loaded row-pair (72 cols)
#define NUNIT (34 * QX)   // 612 load units (34 quad-rows)
#define SDP   76      // sd row stride
#define DDP   38      // sdd row stride

// exact power-of-two weights
#define WG  (1.0f / 67108864.0f)   // 1/(8*8*1024*1024)
#define WP  (1.0f / 8388608.0f)    // 1/(8*1024*1024)
#define WGD (1.0f / 16777216.0f)   // 1/(8*8*512*512)

__device__ float g_part[NBLK];
__device__ unsigned int g_count = 0;

__global__ __launch_bounds__(256) void gloss_fused(
    const float* __restrict__ img_o,
    const float* __restrict__ img_t,
    float* __restrict__ out)
{
    __shared__ float sd[68 * SDP];        // d with halo: 68 x 72 used
    __shared__ float sdd[34 * DDP];       // dd with halo: 34 x 36 used
    __shared__ float red[8][3];
    __shared__ unsigned int s_last;

    const int tid = threadIdx.x;
    const int ty0 = blockIdx.y * TILE;
    const int tx0 = blockIdx.x * TILE;
    const size_t base = (size_t)blockIdx.z * IMG * IMG;

    // ---------- load phase: 3 fully-unrolled predicated iterations ----------
    {
        float4 o0[3], o1[3], t0[3], t1[3];
        int qy[3], ux[3];
        bool act[3];
        #pragma unroll
        for (int i = 0; i < 3; i++) {
            int u = tid + i * 256;
            act[i] = (u < NUNIT);
            int q = u / QX;
            qy[i] = q;
            ux[i] = u - q * QX;
            int gy = ty0 - 2 + 2 * q;
            int gx = tx0 - 4 + 4 * ux[i];
            bool in = act[i] & (gy >= 0) & (gy < IMG) & (gx >= 0) & (gx < IMG);
            float4 z = make_float4(0.f, 0.f, 0.f, 0.f);
            size_t p0 = base + (size_t)gy * IMG + gx;
            o0[i] = in ? *(const float4*)(img_o + p0)       : z;
            o1[i] = in ? *(const float4*)(img_o + p0 + IMG) : z;
            t0[i] = in ? *(const float4*)(img_t + p0)       : z;
            t1[i] = in ? *(const float4*)(img_t + p0 + IMG) : z;
        }
        #pragma unroll
        for (int i = 0; i < 3; i++) {
            if (act[i]) {
                float4 d0 = make_float4(o0[i].x - t0[i].x, o0[i].y - t0[i].y,
                                        o0[i].z - t0[i].z, o0[i].w - t0[i].w);
                float4 d1 = make_float4(o1[i].x - t1[i].x, o1[i].y - t1[i].y,
                                        o1[i].z - t1[i].z, o1[i].w - t1[i].w);
                int sy = 2 * qy[i], sx = 4 * ux[i];
                *(float4*)(sd + sy * SDP + sx)       = d0;
                *(float4*)(sd + (sy + 1) * SDP + sx) = d1;
                float mo0 = fmaxf(fmaxf(o0[i].x, o0[i].y), fmaxf(o1[i].x, o1[i].y));
                float mt0 = fmaxf(fmaxf(t0[i].x, t0[i].y), fmaxf(t1[i].x, t1[i].y));
                float mo1 = fmaxf(fmaxf(o0[i].z, o0[i].w), fmaxf(o1[i].z, o1[i].w));
                float mt1 = fmaxf(fmaxf(t0[i].z, t0[i].w), fmaxf(t1[i].z, t1[i].w));
                *(float2*)(sdd + qy[i] * DDP + 2 * ux[i]) =
                    make_float2(mo0 - mt0, mo1 - mt1);
            }
        }
    }
    __syncthreads();

    // ---------- full-res: pixel loss + 8-dir gradient on d ----------
    float gsum = 0.f, psum = 0.f, gdsum = 0.f;
    {
        int y  = tid >> 2;
        int x0 = (tid & 3) << 4;
        const float* r0 = sd + (y + 1) * SDP + x0 + 3;
        const float* r1 = sd + (y + 2) * SDP + x0 + 3;
        const float* r2 = sd + (y + 3) * SDP + x0 + 3;
        #pragma unroll
        for (int x = 0; x < 16; x++) {
            float c = r1[x + 1];
            psum = fmaf(c, c, psum);
            float e;
            e = c - r0[x];     gsum = fmaf(e, e, gsum);
            e = c - r0[x + 1]; gsum = fmaf(e, e, gsum);
            e = c - r0[x + 2]; gsum = fmaf(e, e, gsum);
            e = c - r1[x];     gsum = fmaf(e, e, gsum);
            e = c - r1[x + 2]; gsum = fmaf(e, e, gsum);
            e = c - r2[x];     gsum = fmaf(e, e, gsum);
            e = c - r2[x + 1]; gsum = fmaf(e, e, gsum);
            e = c - r2[x + 2]; gsum = fmaf(e, e, gsum);
        }
    }

    // ---------- half-res: 8-dir gradient on dd ----------
    {
        int hy  = tid >> 3;
        int hx0 = (tid & 7) << 2;
        const float* r0 = sdd + hy * DDP + hx0 + 1;
        const float* r1 = sdd + (hy + 1) * DDP + hx0 + 1;
        const float* r2 = sdd + (hy + 2) * DDP + hx0 + 1;
        #pragma unroll
        for (int x = 0; x < 4; x++) {
            float c = r1[x + 1];
            float e;
            e = c - r0[x];     gdsum = fmaf(e, e, gdsum);
            e = c - r0[x + 1]; gdsum = fmaf(e, e, gdsum);
            e = c - r0[x + 2]; gdsum = fmaf(e, e, gdsum);
            e = c - r1[x];     gdsum = fmaf(e, e, gdsum);
            e = c - r1[x + 2]; gdsum = fmaf(e, e, gdsum);
            e = c - r2[x];     gdsum = fmaf(e, e, gdsum);
            e = c - r2[x + 1]; gdsum = fmaf(e, e, gdsum);
            e = c - r2[x + 2]; gdsum = fmaf(e, e, gdsum);
        }
    }

    // ---------- block reduction ----------
    #pragma unroll
    for (int off = 16; off; off >>= 1) {
        gsum  += __shfl_down_sync(0xFFFFFFFFu, gsum,  off);
        psum  += __shfl_down_sync(0xFFFFFFFFu, psum,  off);
        gdsum += __shfl_down_sync(0xFFFFFFFFu, gdsum, off);
    }
    int lane = tid & 31, warp = tid >> 5;
    if (lane == 0) {
        red[warp][0] = gsum;
        red[warp][1] = psum;
        red[warp][2] = gdsum;
    }
    __syncthreads();
    if (tid == 0) {
        float g = 0.f, p = 0.f, gd = 0.f;
        #pragma unroll
        for (int w = 0; w < 8; w++) {
            g += red[w][0]; p += red[w][1]; gd += red[w][2];
        }
        int bid = (blockIdx.z * GRIDX + blockIdx.y) * GRIDX + blockIdx.x;
        g_part[bid] = g * WG + p * WP + gd * WGD;
        __threadfence();
        unsigned old = atomicAdd(&g_count, 1u);
        s_last = (old == NBLK - 1) ? 1u : 0u;
    }
    __syncthreads();

    // ---------- last block finalizes ----------
    if (s_last) {
        double s = 0.0;
        #pragma unroll
        for (int i = tid; i < NBLK; i += 256)
            s += (double)g_part[i];
        #pragma unroll
        for (int off = 16; off; off >>= 1)
            s += __shfl_down_sync(0xFFFFFFFFu, s, off);
        __shared__ double dred[8];
        if (lane == 0) dred[warp] = s;
        __syncthreads();
        if (tid == 0) {
            double tot = 0.0;
            #pragma unroll
            for (int w = 0; w < 8; w++) tot += dred[w];
            out[0] = (float)tot;
            g_count = 0;   // reset for next graph replay
        }
    }
}

extern "C" void kernel_launch(void* const* d_in, const int* in_sizes, int n_in,
                              void* d_out, int out_size) {
    const float* img_o = (const float*)d_in[0];
    const float* img_t = (const float*)d_in[1];
    dim3 grid(GRIDX, GRIDX, NIMG);
    gloss_fused<<<grid, 256>>>(img_o, img_t, (float*)d_out);
}

// round 4
// speedup vs baseline: 1.2092x; 1.2092x over previous
#include <cuda_runtime.h>

// GLoss fused: g_loss + p_loss + g_d_loss, single kernel.
//
// Identity used: for the 8-direction zero-padded gradient MSE,
//   sum_{8 dirs} (d[p]-dpad[p+delta])^2
//     = 2 * sum_{delta in {E,S,SE,SW}} (d[p]-dpad[p+delta])^2  + w(p)*d[p]^2
// where w = n_out(p) - 2*m_out(p):
//   top edge +3, bottom edge -3, left edge +1, right edge -1,
//   top corners extra -1, bottom corners extra +1.
//
// 64x64 tile / 256-thread block. Halo: bottom +2 rows (pooling), x widened
// to [-4, +8) for float4 alignment. Last block finalizes (threadfence pattern).

#define IMG   1024
#define HIMG  512
#define NIMG  8
#define TILE  64
#define GRIDX (IMG / TILE)           // 16
#define NBLK  (GRIDX * GRIDX * NIMG) // 2048

#define QX    18                     // float4 units per row-pair (72 cols)
#define NQY   33                     // quad rows (66 rows: ty0 .. ty0+65)
#define NUNIT (NQY * QX)             // 594
#define SDP   76                     // sd row stride (floats)
#define DDP   40                     // sdd row stride (floats)

#define WG  (1.0f / 67108864.0f)     // 1/(8*8*1024*1024)
#define WP  (1.0f / 8388608.0f)      // 1/(8*1024*1024)
#define WGD (1.0f / 16777216.0f)     // 1/(8*8*512*512)

__device__ float g_part[NBLK];
__device__ unsigned int g_count = 0;

__global__ __launch_bounds__(256) void gloss_fused(
    const float* __restrict__ img_o,
    const float* __restrict__ img_t,
    float* __restrict__ out)
{
    __shared__ float sd[66 * SDP];       // d: rows ty0..ty0+65, cols tx0-4..tx0+67
    __shared__ float sdd[33 * DDP];      // dd: idx = (hgx - hx0b) + 4, rows hy0..hy0+32
    __shared__ float red[8];
    __shared__ unsigned int s_last;

    const int tid = threadIdx.x;
    const int ty0 = blockIdx.y * TILE;
    const int tx0 = blockIdx.x * TILE;
    const size_t base = (size_t)blockIdx.z * IMG * IMG;

    // ---------------- load + pool phase (3 unrolled iterations) ----------------
    {
        float4 o0[3], o1[3], t0[3], t1[3];
        int qy[3], ux[3];
        bool act[3];
        #pragma unroll
        for (int i = 0; i < 3; i++) {
            int u = tid + i * 256;
            act[i] = (u < NUNIT);
            int q = u / QX;
            qy[i] = q;
            ux[i] = u - q * QX;
            int gy = ty0 + 2 * q;
            int gx = tx0 - 4 + 4 * ux[i];
            bool colok = (gx >= 0) & (gx < IMG);
            bool in0 = act[i] & colok & (gy < IMG);
            bool in1 = act[i] & colok & (gy + 1 < IMG);
            float4 z = make_float4(0.f, 0.f, 0.f, 0.f);
            size_t p0 = base + (size_t)gy * IMG + gx;
            o0[i] = in0 ? *(const float4*)(img_o + p0)       : z;
            t0[i] = in0 ? *(const float4*)(img_t + p0)       : z;
            o1[i] = in1 ? *(const float4*)(img_o + p0 + IMG) : z;
            t1[i] = in1 ? *(const float4*)(img_t + p0 + IMG) : z;
        }
        #pragma unroll
        for (int i = 0; i < 3; i++) {
            if (act[i]) {
                float4 d0 = make_float4(o0[i].x - t0[i].x, o0[i].y - t0[i].y,
                                        o0[i].z - t0[i].z, o0[i].w - t0[i].w);
                float4 d1 = make_float4(o1[i].x - t1[i].x, o1[i].y - t1[i].y,
                                        o1[i].z - t1[i].z, o1[i].w - t1[i].w);
                int sy = 2 * qy[i], sx = 4 * ux[i];
                *(float4*)(sd + sy * SDP + sx)       = d0;
                *(float4*)(sd + (sy + 1) * SDP + sx) = d1;
                float mo0 = fmaxf(fmaxf(o0[i].x, o0[i].y), fmaxf(o1[i].x, o1[i].y));
                float mt0 = fmaxf(fmaxf(t0[i].x, t0[i].y), fmaxf(t1[i].x, t1[i].y));
                float mo1 = fmaxf(fmaxf(o0[i].z, o0[i].w), fmaxf(o1[i].z, o1[i].w));
                float mt1 = fmaxf(fmaxf(t0[i].z, t0[i].w), fmaxf(t1[i].z, t1[i].w));
                *(float2*)(sdd + qy[i] * DDP + 2 * ux[i] + 2) =
                    make_float2(mo0 - mt0, mo1 - mt1);
            }
        }
    }
    __syncthreads();

    // ---------------- full-res: pixel + 4-dir gradient (x2) + boundary ----------------
    // thread: row y = tid&63, strip = tid>>6 (16 px), processed in 2 halves of 8.
    float gsum = 0.f, psum = 0.f, bsum = 0.f, gdsum = 0.f, bdsum = 0.f;
    {
        const int y  = tid & 63;
        const int x0 = (tid >> 6) << 4;
        const int gy = ty0 + y;
        #pragma unroll
        for (int h = 0; h < 2; h++) {
            const int x0h = x0 + 8 * h;
            const float* r1 = sd + y * SDP + x0h + 4;
            const float* r2 = sd + (y + 1) * SDP + x0h + 4;
            float c[9], b[10];
            float4 v;
            v = *(const float4*)(r1 + 0); c[0]=v.x; c[1]=v.y; c[2]=v.z; c[3]=v.w;
            v = *(const float4*)(r1 + 4); c[4]=v.x; c[5]=v.y; c[6]=v.z; c[7]=v.w;
            c[8] = r1[8];
            v = *(const float4*)(r2 - 4); b[0] = v.w;
            v = *(const float4*)(r2 + 0); b[1]=v.x; b[2]=v.y; b[3]=v.z; b[4]=v.w;
            v = *(const float4*)(r2 + 4); b[5]=v.x; b[6]=v.y; b[7]=v.z; b[8]=v.w;
            b[9] = r2[8];
            #pragma unroll
            for (int i = 0; i < 8; i++) {
                float cc = c[i];
                psum = fmaf(cc, cc, psum);
                float e;
                e = cc - c[i + 1]; gsum = fmaf(e, e, gsum);  // E
                e = cc - b[i];     gsum = fmaf(e, e, gsum);  // SW
                e = cc - b[i + 1]; gsum = fmaf(e, e, gsum);  // S
                e = cc - b[i + 2]; gsum = fmaf(e, e, gsum);  // SE
            }
            // boundary correction (rare branch)
            bool lb = (tx0 == 0) && (x0h == 0);
            bool rb = (tx0 == IMG - TILE) && (x0h == 56);
            if ((gy == 0) | (gy == IMG - 1) | lb | rb) {
                #pragma unroll
                for (int i = 0; i < 8; i++) {
                    int gx = tx0 + x0h + i;
                    float w = 0.f;
                    if (gy == 0)       w += 3.f;
                    if (gy == IMG - 1) w -= 3.f;
                    if (gx == 0)       w += 1.f;
                    if (gx == IMG - 1) w -= 1.f;
                    bool xe = (gx == 0) | (gx == IMG - 1);
                    if ((gy == 0) & xe)       w -= 1.f;
                    if ((gy == IMG - 1) & xe) w += 1.f;
                    bsum = fmaf(w * c[i], c[i], bsum);
                }
            }
        }
    }

    // ---------------- half-res: 4-dir gradient (x2) + boundary on dd ----------------
    {
        const int hy   = tid >> 3;            // 0..31
        const int hx0s = (tid & 7) << 2;      // 0,4,...,28
        const int hy0b = ty0 >> 1;
        const int hx0b = tx0 >> 1;
        const float* r1 = sdd + hy * DDP + hx0s + 4;
        const float* r2 = sdd + (hy + 1) * DDP + hx0s + 4;
        float c[5], b[6];
        float4 v;
        v = *(const float4*)(r1 + 0); c[0]=v.x; c[1]=v.y; c[2]=v.z; c[3]=v.w;
        c[4] = r1[4];
        v = *(const float4*)(r2 - 4); b[0] = v.w;
        v = *(const float4*)(r2 + 0); b[1]=v.x; b[2]=v.y; b[3]=v.z; b[4]=v.w;
        b[5] = r2[4];
        #pragma unroll
        for (int j = 0; j < 4; j++) {
            float cc = c[j];
            float e;
            e = cc - c[j + 1]; gdsum = fmaf(e, e, gdsum);
            e = cc - b[j];     gdsum = fmaf(e, e, gdsum);
            e = cc - b[j + 1]; gdsum = fmaf(e, e, gdsum);
            e = cc - b[j + 2]; gdsum = fmaf(e, e, gdsum);
        }
        const int hgy = hy0b + hy;
        bool lb = (hx0b == 0) && (hx0s == 0);
        bool rb = (hx0b == HIMG - 32) && (hx0s == 28);
        if ((hgy == 0) | (hgy == HIMG - 1) | lb | rb) {
            #pragma unroll
            for (int j = 0; j < 4; j++) {
                int hgx = hx0b + hx0s + j;
                float w = 0.f;
                if (hgy == 0)        w += 3.f;
                if (hgy == HIMG - 1) w -= 3.f;
                if (hgx == 0)        w += 1.f;
                if (hgx == HIMG - 1) w -= 1.f;
                bool xe = (hgx == 0) | (hgx == HIMG - 1);
                if ((hgy == 0) & xe)        w -= 1.f;
                if ((hgy == HIMG - 1) & xe) w += 1.f;
                bdsum = fmaf(w * c[j], c[j], bdsum);
            }
        }
    }

    // ---------------- single-value block reduction ----------------
    float val = fmaf(2.f, gsum, bsum) * WG + psum * WP
              + fmaf(2.f, gdsum, bdsum) * WGD;
    #pragma unroll
    for (int off = 16; off; off >>= 1)
        val += __shfl_down_sync(0xFFFFFFFFu, val, off);
    int lane = tid & 31, warp = tid >> 5;
    if (lane == 0) red[warp] = val;
    __syncthreads();
    if (tid == 0) {
        float s = 0.f;
        #pragma unroll
        for (int w = 0; w < 8; w++) s += red[w];
        int bid = (blockIdx.z * GRIDX + blockIdx.y) * GRIDX + blockIdx.x;
        g_part[bid] = s;
        __threadfence();
        unsigned old = atomicAdd(&g_count, 1u);
        s_last = (old == NBLK - 1) ? 1u : 0u;
    }
    __syncthreads();

    // ---------------- last block finalizes ----------------
    if (s_last) {
        double s = 0.0;
        #pragma unroll
        for (int i = tid; i < NBLK; i += 256)
            s += (double)g_part[i];
        #pragma unroll
        for (int off = 16; off; off >>= 1)
            s += __shfl_down_sync(0xFFFFFFFFu, s, off);
        __shared__ double dred[8];
        if (lane == 0) dred[warp] = s;
        __syncthreads();
        if (tid == 0) {
            double tot = 0.0;
            #pragma unroll
            for (int w = 0; w < 8; w++) tot += dred[w];
            out[0] = (float)tot;
            g_count = 0;   // reset for next graph replay
        }
    }
}

extern "C" void kernel_launch(void* const* d_in, const int* in_sizes, int n_in,
                              void* d_out, int out_size) {
    const float* img_o = (const float*)d_in[0];
    const float* img_t = (const float*)d_in[1];
    dim3 grid(GRIDX, GRIDX, NIMG);
    gloss_fused<<<grid, 256>>>(img_o, img_t, (float*)d_out);
}

// round 5
// speedup vs baseline: 1.3401x; 1.1083x over previous
#include <cuda_runtime.h>

// GLoss fused, barrier-free register streaming.
//
// Identity (validated R4): 8-dir zero-padded gradient MSE sum
//   = 2 * sum_{delta in {E,S,SE,SW}} (d[p]-dpad[p+delta])^2 + w(p)*d[p]^2,
// w = +3 top row, -3 bottom row, +1 left col, -1 right col,
//     top corners extra -1, bottom corners extra +1.
//
// Block = 256 threads = one full 1024-col row (float4/thread).
// Streams NPAIR=9 row pairs (16 owned rows + 2 halo rows for pooling).
// Horizontal neighbors via warp shuffle; warp-edge columns via predicated
// float2 loads on lanes 0/31 (L1 hits). No smem in the hot path.

#define IMG   1024
#define HIMG  512
#define NIMG  8
#define ROWS  16
#define NPAIR 9                   // (ROWS/2 + 1) pairs streamed
#define GRIDY (IMG / ROWS)        // 64
#define NBLK  (GRIDY * NIMG)      // 512

#define WG  (1.0f / 67108864.0f)  // 1/(8*8*1024*1024)
#define WP  (1.0f / 8388608.0f)   // 1/(8*1024*1024)
#define WGD (1.0f / 16777216.0f)  // 1/(8*8*512*512)

__device__ float g_part[NBLK];
__device__ unsigned int g_count = 0;

__device__ __forceinline__ float sq(float x) { return x * x; }

__device__ __forceinline__ float bweight(int gy, int gx, int n) {
    float w = 0.f;
    if (gy == 0)     w += 3.f;
    if (gy == n - 1) w -= 3.f;
    if (gx == 0)     w += 1.f;
    if (gx == n - 1) w -= 1.f;
    bool xe = (gx == 0) | (gx == n - 1);
    if ((gy == 0) & xe)     w -= 1.f;
    if ((gy == n - 1) & xe) w += 1.f;
    return w;
}

__global__ __launch_bounds__(256, 3) void gloss_stream(
    const float* __restrict__ img_o,
    const float* __restrict__ img_t,
    float* __restrict__ out)
{
    const int tid  = threadIdx.x;
    const int lane = tid & 31;
    const int ry0  = blockIdx.x * ROWS;
    const size_t base = (size_t)blockIdx.y * IMG * IMG;
    const int gx0 = tid << 2;

    const bool isL = (lane == 0)  && (tid != 0);
    const bool isR = (lane == 31) && (tid != 255);

    const float* po_base = img_o + base + gx0;
    const float* pt_base = img_t + base + gx0;

    float gsum = 0.f, psum = 0.f, bsum = 0.f, gdsum = 0.f, bdsum = 0.f;
    float4 dprev  = make_float4(0.f, 0.f, 0.f, 0.f);
    float2 ddprev = make_float2(0.f, 0.f);
    float  ddpR   = 0.f;

    // load pair 0 (rows ry0, ry0+1 always in image)
    float4 co0, co1, ct0, ct1;
    {
        const float* po = po_base + (size_t)ry0 * IMG;
        const float* pt = pt_base + (size_t)ry0 * IMG;
        co0 = *(const float4*)po;  co1 = *(const float4*)(po + IMG);
        ct0 = *(const float4*)pt;  ct1 = *(const float4*)(pt + IMG);
    }

    #pragma unroll 1
    for (int j = 0; j < NPAIR; j++) {
        const int gy0 = ry0 + 2 * j;
        const int gy1 = gy0 + 1;

        // ---- prefetch next pair ----
        float4 no0, no1, nt0, nt1;
        {
            float4 z = make_float4(0.f, 0.f, 0.f, 0.f);
            no0 = no1 = nt0 = nt1 = z;
            if (j + 1 < NPAIR) {
                int ng = gy0 + 2;
                const float* po = po_base + (size_t)ng * IMG;
                const float* pt = pt_base + (size_t)ng * IMG;
                bool i0 = ng < IMG, i1 = ng + 1 < IMG;
                if (i0) { no0 = *(const float4*)po;        nt0 = *(const float4*)pt; }
                if (i1) { no1 = *(const float4*)(po + IMG); nt1 = *(const float4*)(pt + IMG); }
            }
        }

        // ---- warp-edge neighbor loads (lanes 0/31 only; L1 hits) ----
        float dL0 = 0.f, dL1 = 0.f, dR0 = 0.f, dR1 = 0.f, ddL = 0.f, ddR = 0.f;
        if (isL | isR) {
            int off = isL ? (gx0 - 2) : (gx0 + 4);
            float2 z2 = make_float2(0.f, 0.f);
            float2 a0 = z2, a1 = z2, b0 = z2, b1 = z2;
            const float* po = img_o + base + off;
            const float* pt = img_t + base + off;
            if (gy0 < IMG) { a0 = *(const float2*)(po + (size_t)gy0 * IMG);
                             b0 = *(const float2*)(pt + (size_t)gy0 * IMG); }
            if (gy1 < IMG) { a1 = *(const float2*)(po + (size_t)gy1 * IMG);
                             b1 = *(const float2*)(pt + (size_t)gy1 * IMG); }
            float pdd = fmaxf(fmaxf(a0.x, a0.y), fmaxf(a1.x, a1.y))
                      - fmaxf(fmaxf(b0.x, b0.y), fmaxf(b1.x, b1.y));
            if (isL) { dL0 = a0.y - b0.y; dL1 = a1.y - b1.y; ddL = pdd; }
            else     { dR0 = a0.x - b0.x; dR1 = a1.x - b1.x; ddR = pdd; }
        }

        // ---- d and pooled dd ----
        float4 d0 = make_float4(co0.x - ct0.x, co0.y - ct0.y, co0.z - ct0.z, co0.w - ct0.w);
        float4 d1 = make_float4(co1.x - ct1.x, co1.y - ct1.y, co1.z - ct1.z, co1.w - ct1.w);
        float2 dd;
        dd.x = fmaxf(fmaxf(co0.x, co0.y), fmaxf(co1.x, co1.y))
             - fmaxf(fmaxf(ct0.x, ct0.y), fmaxf(ct1.x, ct1.y));
        dd.y = fmaxf(fmaxf(co0.z, co0.w), fmaxf(co1.z, co1.w))
             - fmaxf(fmaxf(ct0.z, ct0.w), fmaxf(ct1.z, ct1.w));

        // ---- horizontal neighbors via shuffle (+ edge fixups) ----
        float t;
        t = __shfl_up_sync(0xFFFFFFFFu, d0.w, 1);  float n0L = (lane == 0)  ? dL0 : t;
        t = __shfl_down_sync(0xFFFFFFFFu, d0.x, 1); float n0R = (lane == 31) ? dR0 : t;
        t = __shfl_up_sync(0xFFFFFFFFu, d1.w, 1);  float n1L = (lane == 0)  ? dL1 : t;
        t = __shfl_down_sync(0xFFFFFFFFu, d1.x, 1); float n1R = (lane == 31) ? dR1 : t;
        t = __shfl_up_sync(0xFFFFFFFFu, dd.y, 1);  float nddL = (lane == 0)  ? ddL : t;
        t = __shfl_down_sync(0xFFFFFFFFu, dd.x, 1); float nddR = (lane == 31) ? ddR : t;

        if (j > 0) {
            // S/SW/SE centered at dprev (row gy0-1, always owned)
            gsum += sq(dprev.x - d0.x) + sq(dprev.x - n0L)  + sq(dprev.x - d0.y)
                  + sq(dprev.y - d0.y) + sq(dprev.y - d0.x) + sq(dprev.y - d0.z)
                  + sq(dprev.z - d0.z) + sq(dprev.z - d0.y) + sq(dprev.z - d0.w)
                  + sq(dprev.w - d0.w) + sq(dprev.w - d0.z) + sq(dprev.w - n0R);
            // dd: E centered at ddprev + S/SW/SE centered at ddprev
            gdsum += sq(ddprev.x - ddprev.y) + sq(ddprev.y - ddpR)
                   + sq(ddprev.x - dd.x) + sq(ddprev.x - nddL) + sq(ddprev.x - dd.y)
                   + sq(ddprev.y - dd.y) + sq(ddprev.y - dd.x) + sq(ddprev.y - nddR);
        }

        if (j < NPAIR - 1) {
            // pixel loss (owned rows)
            psum += sq(d0.x) + sq(d0.y) + sq(d0.z) + sq(d0.w)
                  + sq(d1.x) + sq(d1.y) + sq(d1.z) + sq(d1.w);
            // E within owned rows
            gsum += sq(d0.x - d0.y) + sq(d0.y - d0.z) + sq(d0.z - d0.w) + sq(d0.w - n0R)
                  + sq(d1.x - d1.y) + sq(d1.y - d1.z) + sq(d1.z - d1.w) + sq(d1.w - n1R);
            // S/SW/SE centered at d0 (row gy0)
            gsum += sq(d0.x - d1.x) + sq(d0.x - n1L)  + sq(d0.x - d1.y)
                  + sq(d0.y - d1.y) + sq(d0.y - d1.x) + sq(d0.y - d1.z)
                  + sq(d0.z - d1.z) + sq(d0.z - d1.y) + sq(d0.z - d1.w)
                  + sq(d0.w - d1.w) + sq(d0.w - d1.z) + sq(d0.w - n1R);

            // boundary corrections (rare / edge threads only)
            if ((gy0 == 0) | (gy1 == IMG - 1) | (tid == 0) | (tid == 255)) {
                bsum += bweight(gy0, gx0 + 0, IMG) * sq(d0.x)
                      + bweight(gy0, gx0 + 1, IMG) * sq(d0.y)
                      + bweight(gy0, gx0 + 2, IMG) * sq(d0.z)
                      + bweight(gy0, gx0 + 3, IMG) * sq(d0.w)
                      + bweight(gy1, gx0 + 0, IMG) * sq(d1.x)
                      + bweight(gy1, gx0 + 1, IMG) * sq(d1.y)
                      + bweight(gy1, gx0 + 2, IMG) * sq(d1.z)
                      + bweight(gy1, gx0 + 3, IMG) * sq(d1.w);
            }
            int hgy = (ry0 >> 1) + j;
            if ((hgy == 0) | (hgy == HIMG - 1) | (tid == 0) | (tid == 255)) {
                bdsum += bweight(hgy, 2 * tid,     HIMG) * sq(dd.x)
                       + bweight(hgy, 2 * tid + 1, HIMG) * sq(dd.y);
            }
        }

        dprev = d1; ddprev = dd; ddpR = nddR;
        co0 = no0; co1 = no1; ct0 = nt0; ct1 = nt1;
    }

    // ---------------- block reduction + last-block finalize ----------------
    __shared__ float red[8];
    __shared__ unsigned int s_last;
    float val = fmaf(2.f, gsum, bsum) * WG + psum * WP
              + fmaf(2.f, gdsum, bdsum) * WGD;
    #pragma unroll
    for (int off = 16; off; off >>= 1)
        val += __shfl_down_sync(0xFFFFFFFFu, val, off);
    int warp = tid >> 5;
    if (lane == 0) red[warp] = val;
    __syncthreads();
    if (tid == 0) {
        float s = 0.f;
        #pragma unroll
        for (int w = 0; w < 8; w++) s += red[w];
        int bid = blockIdx.y * GRIDY + blockIdx.x;
        g_part[bid] = s;
        __threadfence();
        unsigned old = atomicAdd(&g_count, 1u);
        s_last = (old == NBLK - 1) ? 1u : 0u;
    }
    __syncthreads();

    if (s_last) {
        double s = 0.0;
        #pragma unroll
        for (int i = tid; i < NBLK; i += 256)
            s += (double)g_part[i];
        #pragma unroll
        for (int off = 16; off; off >>= 1)
            s += __shfl_down_sync(0xFFFFFFFFu, s, off);
        __shared__ double dred[8];
        if (lane == 0) dred[warp] = s;
        __syncthreads();
        if (tid == 0) {
            double tot = 0.0;
            #pragma unroll
            for (int w = 0; w < 8; w++) tot += dred[w];
            out[0] = (float)tot;
            g_count = 0;   // reset for next graph replay
        }
    }
}

extern "C" void kernel_launch(void* const* d_in, const int* in_sizes, int n_in,
                              void* d_out, int out_size) {
    const float* img_o = (const float*)d_in[0];
    const float* img_t = (const float*)d_in[1];
    dim3 grid(GRIDY, NIMG);
    gloss_stream<<<grid, 256>>>(img_o, img_t, (float*)d_out);
}

// round 6
// speedup vs baseline: 1.5028x; 1.1214x over previous
#include <cuda_runtime.h>

// GLoss fused, correlation form, barrier-free register streaming.
//
// Identity (zero-padded 8-dir gradient MSE):
//   G = 16*S - B - 4*(C_E + C_S + C_SE + C_SW)
//   S = sum d^2,  C_delta = sum d[p]*d[p+delta],
//   B = sum w(p) d[p]^2,  w = 3*ry + 3*cx - ry*cx,
//     ry = [y==0]+[y==N-1], cx = [x==0]+[x==N-1].
// Full-res combined with pixel loss (WP = 8*WG):  WG*(24S - B - 4C).
// Half-res (dd = maxpool2(o)-maxpool2(t)):        WGD*(16S - B - 4C).
//
// Block = 128 threads = 512 cols (float4/thread), streams 9 row pairs
// (16 owned rows + 2 for pooling/vertical pairing). Right-neighbor values via
// shfl_down; warp-edge col via predicated float2 loads on lane 31 (L2 hits).

#define IMG   1024
#define HIMG  512
#define NIMG  8
#define ROWS  16
#define NPAIR 9
#define GRIDY (IMG / ROWS)            // 64
#define NBLK  (2 * GRIDY * NIMG)      // 1024

#define WG  (1.0f / 67108864.0f)      // 1/(8*8*1024*1024)
#define WGD (1.0f / 16777216.0f)      // 1/(8*8*512*512)

__device__ float g_part[NBLK];
__device__ unsigned int g_count = 0;

__device__ __forceinline__ float bw(int y, int x, int n) {
    int ry = (y == 0) + (y == n - 1);
    int cx = (x == 0) + (x == n - 1);
    return (float)(3 * ry + 3 * cx - ry * cx);
}

__global__ __launch_bounds__(128) void gloss_corr(
    const float* __restrict__ img_o,
    const float* __restrict__ img_t,
    float* __restrict__ out)
{
    const int tid  = threadIdx.x;
    const int lane = tid & 31;
    const int ry0  = blockIdx.y * ROWS;
    const size_t base = (size_t)blockIdx.z * IMG * IMG;
    const int gx0 = blockIdx.x * 512 + (tid << 2);
    const int hx0 = gx0 >> 1;

    const bool isR     = (lane == 31);
    const bool nbr_in  = (gx0 + 4 < IMG);
    const bool col_edge = (gx0 == 0) | (gx0 + 4 == IMG);

    const float* po_base = img_o + base + gx0;
    const float* pt_base = img_t + base + gx0;

    float sa = 0.f, ca = 0.f, ba = 0.f;     // full-res S, C, B
    float sh = 0.f, ch = 0.f, bh = 0.f;     // half-res
    float4 dprev = make_float4(0.f, 0.f, 0.f, 0.f);
    float2 ddprev = make_float2(0.f, 0.f);
    float pnd1 = 0.f, pnddx = 0.f;

    // pair 0 (rows ry0, ry0+1 always in image)
    float4 co0, co1, ct0, ct1;
    {
        const float* po = po_base + (size_t)ry0 * IMG;
        const float* pt = pt_base + (size_t)ry0 * IMG;
        co0 = *(const float4*)po;  co1 = *(const float4*)(po + IMG);
        ct0 = *(const float4*)pt;  ct1 = *(const float4*)(pt + IMG);
    }

    #pragma unroll 1
    for (int j = 0; j < NPAIR; j++) {
        const int gy0 = ry0 + 2 * j;
        const int gy1 = gy0 + 1;

        // ---- prefetch next pair ----
        float4 no0, no1, nt0, nt1;
        {
            float4 z = make_float4(0.f, 0.f, 0.f, 0.f);
            no0 = no1 = nt0 = nt1 = z;
            if (j + 1 < NPAIR) {
                int ng = gy0 + 2;
                const float* po = po_base + (size_t)ng * IMG;
                const float* pt = pt_base + (size_t)ng * IMG;
                if (ng < IMG)     { no0 = *(const float4*)po;         nt0 = *(const float4*)pt; }
                if (ng + 1 < IMG) { no1 = *(const float4*)(po + IMG); nt1 = *(const float4*)(pt + IMG); }
            }
        }

        // ---- right-edge neighbor (lane 31 only) ----
        float dR0 = 0.f, dR1 = 0.f, pddR = 0.f;
        if (isR && nbr_in) {
            float2 z2 = make_float2(0.f, 0.f);
            float2 a0 = z2, a1 = z2, b0 = z2, b1 = z2;
            const float* po = img_o + base + gx0 + 4;
            const float* pt = img_t + base + gx0 + 4;
            if (gy0 < IMG) { a0 = *(const float2*)(po + (size_t)gy0 * IMG);
                             b0 = *(const float2*)(pt + (size_t)gy0 * IMG); }
            if (gy1 < IMG) { a1 = *(const float2*)(po + (size_t)gy1 * IMG);
                             b1 = *(const float2*)(pt + (size_t)gy1 * IMG); }
            dR0 = a0.x - b0.x;
            dR1 = a1.x - b1.x;
            pddR = fmaxf(fmaxf(a0.x, a0.y), fmaxf(a1.x, a1.y))
                 - fmaxf(fmaxf(b0.x, b0.y), fmaxf(b1.x, b1.y));
        }

        // ---- d and pooled dd ----
        float4 d0 = make_float4(co0.x - ct0.x, co0.y - ct0.y, co0.z - ct0.z, co0.w - ct0.w);
        float4 d1 = make_float4(co1.x - ct1.x, co1.y - ct1.y, co1.z - ct1.z, co1.w - ct1.w);
        float2 dd;
        dd.x = fmaxf(fmaxf(co0.x, co0.y), fmaxf(co1.x, co1.y))
             - fmaxf(fmaxf(ct0.x, ct0.y), fmaxf(ct1.x, ct1.y));
        dd.y = fmaxf(fmaxf(co0.z, co0.w), fmaxf(co1.z, co1.w))
             - fmaxf(fmaxf(ct0.z, ct0.w), fmaxf(ct1.z, ct1.w));

        // ---- +1 neighbors via shuffle (lane31 -> loaded values) ----
        float t;
        t = __shfl_down_sync(0xFFFFFFFFu, d0.x, 1); float nd0  = isR ? dR0  : t;
        t = __shfl_down_sync(0xFFFFFFFFu, d1.x, 1); float nd1  = isR ? dR1  : t;
        t = __shfl_down_sync(0xFFFFFFFFu, dd.x, 1); float nddR = isR ? pddR : t;

        // ---- correlations with previous row (dprev=0 at j=0 -> no-op) ----
        ca = fmaf(dprev.x, d0.x, ca); ca = fmaf(dprev.y, d0.y, ca);   // S
        ca = fmaf(dprev.z, d0.z, ca); ca = fmaf(dprev.w, d0.w, ca);
        ca = fmaf(dprev.x, d0.y, ca); ca = fmaf(dprev.y, d0.z, ca);   // SE
        ca = fmaf(dprev.z, d0.w, ca); ca = fmaf(dprev.w, nd0,  ca);
        ca = fmaf(dprev.y, d0.x, ca); ca = fmaf(dprev.z, d0.y, ca);   // SW
        ca = fmaf(dprev.w, d0.z, ca); ca = fmaf(pnd1,    d0.w, ca);

        ch = fmaf(ddprev.x, dd.x, ch); ch = fmaf(ddprev.y, dd.y, ch); // S
        ch = fmaf(ddprev.x, dd.y, ch); ch = fmaf(ddprev.y, nddR, ch); // SE
        ch = fmaf(ddprev.y, dd.x, ch); ch = fmaf(pnddx,    dd.y, ch); // SW

        if (j < NPAIR - 1) {
            // owned rows: S, E, intra-pair S/SE/SW
            sa = fmaf(d0.x, d0.x, sa); sa = fmaf(d0.y, d0.y, sa);
            sa = fmaf(d0.z, d0.z, sa); sa = fmaf(d0.w, d0.w, sa);
            sa = fmaf(d1.x, d1.x, sa); sa = fmaf(d1.y, d1.y, sa);
            sa = fmaf(d1.z, d1.z, sa); sa = fmaf(d1.w, d1.w, sa);

            ca = fmaf(d0.x, d0.y, ca); ca = fmaf(d0.y, d0.z, ca);     // E row0
            ca = fmaf(d0.z, d0.w, ca); ca = fmaf(d0.w, nd0,  ca);
            ca = fmaf(d1.x, d1.y, ca); ca = fmaf(d1.y, d1.z, ca);     // E row1
            ca = fmaf(d1.z, d1.w, ca); ca = fmaf(d1.w, nd1,  ca);
            ca = fmaf(d0.x, d1.x, ca); ca = fmaf(d0.y, d1.y, ca);     // S pair
            ca = fmaf(d0.z, d1.z, ca); ca = fmaf(d0.w, d1.w, ca);
            ca = fmaf(d0.x, d1.y, ca); ca = fmaf(d0.y, d1.z, ca);     // SE pair
            ca = fmaf(d0.z, d1.w, ca); ca = fmaf(d0.w, nd1,  ca);
            ca = fmaf(d0.y, d1.x, ca); ca = fmaf(d0.z, d1.y, ca);     // SW pair
            ca = fmaf(d0.w, d1.z, ca); ca = fmaf(nd0,  d1.w, ca);

            sh = fmaf(dd.x, dd.x, sh); sh = fmaf(dd.y, dd.y, sh);
            ch = fmaf(dd.x, dd.y, ch); ch = fmaf(dd.y, nddR, ch);     // E half

            // boundary corrections (rare)
            if (col_edge | (gy0 == 0) | (gy1 == IMG - 1)) {
                ba = fmaf(bw(gy0, gx0,     IMG) * d0.x, d0.x, ba);
                ba = fmaf(bw(gy0, gx0 + 1, IMG) * d0.y, d0.y, ba);
                ba = fmaf(bw(gy0, gx0 + 2, IMG) * d0.z, d0.z, ba);
                ba = fmaf(bw(gy0, gx0 + 3, IMG) * d0.w, d0.w, ba);
                ba = fmaf(bw(gy1, gx0,     IMG) * d1.x, d1.x, ba);
                ba = fmaf(bw(gy1, gx0 + 1, IMG) * d1.y, d1.y, ba);
                ba = fmaf(bw(gy1, gx0 + 2, IMG) * d1.z, d1.z, ba);
                ba = fmaf(bw(gy1, gx0 + 3, IMG) * d1.w, d1.w, ba);
            }
            int hgy = (ry0 >> 1) + j;
            if (col_edge | (hgy == 0) | (hgy == HIMG - 1)) {
                bh = fmaf(bw(hgy, hx0,     HIMG) * dd.x, dd.x, bh);
                bh = fmaf(bw(hgy, hx0 + 1, HIMG) * dd.y, dd.y, bh);
            }
        }

        dprev = d1; ddprev = dd; pnd1 = nd1; pnddx = nddR;
        co0 = no0; co1 = no1; ct0 = nt0; ct1 = nt1;
    }

    // ---------------- block reduction + last-block finalize ----------------
    __shared__ float red[4];
    __shared__ unsigned int s_last;
    float val = (24.f * sa - ba - 4.f * ca) * WG
              + (16.f * sh - bh - 4.f * ch) * WGD;
    #pragma unroll
    for (int off = 16; off; off >>= 1)
        val += __shfl_down_sync(0xFFFFFFFFu, val, off);
    int warp = tid >> 5;
    if (lane == 0) red[warp] = val;
    __syncthreads();
    if (tid == 0) {
        float s = red[0] + red[1] + red[2] + red[3];
        int bid = (blockIdx.z * GRIDY + blockIdx.y) * 2 + blockIdx.x;
        g_part[bid] = s;
        __threadfence();
        unsigned old = atomicAdd(&g_count, 1u);
        s_last = (old == NBLK - 1) ? 1u : 0u;
    }
    __syncthreads();

    if (s_last) {
        double s = 0.0;
        #pragma unroll
        for (int i = tid; i < NBLK; i += 128)
            s += (double)g_part[i];
        #pragma unroll
        for (int off = 16; off; off >>= 1)
            s += __shfl_down_sync(0xFFFFFFFFu, s, off);
        __shared__ double dred[4];
        if (lane == 0) dred[warp] = s;
        __syncthreads();
        if (tid == 0) {
            out[0] = (float)(dred[0] + dred[1] + dred[2] + dred[3]);
            g_count = 0;   // reset for next graph replay
        }
    }
}

extern "C" void kernel_launch(void* const* d_in, const int* in_sizes, int n_in,
                              void* d_out, int out_size) {
    const float* img_o = (const float*)d_in[0];
    const float* img_t = (const float*)d_in[1];
    dim3 grid(2, GRIDY, NIMG);
    gloss_corr<<<grid, 128>>>(img_o, img_t, (float*)d_out);
}

// round 7
// speedup vs baseline: 1.6815x; 1.1189x over previous
#include <cuda_runtime.h>

// GLoss fused, correlation form, register streaming, low-reg variant.
//
// Identity (validated R6):
//   G = 16*S - B - 4*(C_E + C_S + C_SE + C_SW),  B = sum w(p) d[p]^2,
//   w = 3*ry + 3*cx - ry*cx.  Full-res + pixel loss: WG*(24S - B - 4C).
//   Half-res: WGD*(16S - B - 4C) on dd = maxpool2(o) - maxpool2(t).
//
// Block = 128 threads = 512 cols (float4/thread), streams 9 row pairs.
// Loop-carried state is differences only (d0,d1,dd + lane-31 edges); raw
// prefetched values are converted at the END of the iteration so their
// loads are covered by the FMA block. Accumulators split to shorten chains.

#define IMG   1024
#define HIMG  512
#define NIMG  8
#define ROWS  16
#define NPAIR 9
#define GRIDY (IMG / ROWS)            // 64
#define NBLK  (2 * GRIDY * NIMG)      // 1024

#define WG  (1.0f / 67108864.0f)      // 1/(8*8*1024*1024)
#define WGD (1.0f / 16777216.0f)      // 1/(8*8*512*512)

__device__ float g_part[NBLK];
__device__ unsigned int g_count = 0;

__device__ __forceinline__ float bw(int y, int x, int n) {
    int ry = (y == 0) + (y == n - 1);
    int cx = (x == 0) + (x == n - 1);
    return (float)(3 * ry + 3 * cx - ry * cx);
}

__device__ __forceinline__ float max4(float a, float b, float c, float d) {
    return fmaxf(fmaxf(a, b), fmaxf(c, d));
}

__global__ __launch_bounds__(128, 8) void gloss_corr(
    const float* __restrict__ img_o,
    const float* __restrict__ img_t,
    float* __restrict__ out)
{
    const int tid  = threadIdx.x;
    const int lane = tid & 31;
    const int ry0  = blockIdx.y * ROWS;
    const size_t base = (size_t)blockIdx.z * IMG * IMG;
    const int gx0 = blockIdx.x * 512 + (tid << 2);
    const int hx0 = gx0 >> 1;

    const bool isR      = (lane == 31);
    const bool edge_ld  = isR && (gx0 + 4 < IMG);
    const bool col_edge = (gx0 == 0) | (gx0 + 4 == IMG);

    const float* po_base = img_o + base + gx0;
    const float* pt_base = img_t + base + gx0;

    // ---- carried state: differences for current pair ----
    float4 d0, d1;
    float2 dd;
    float  eR0 = 0.f, eR1 = 0.f, eddR = 0.f;   // lane-31 edge diffs

    // prologue: pair 0 (rows ry0, ry0+1 always in image)
    {
        const float* po = po_base + (size_t)ry0 * IMG;
        const float* pt = pt_base + (size_t)ry0 * IMG;
        float4 o0 = *(const float4*)po,        o1 = *(const float4*)(po + IMG);
        float4 t0 = *(const float4*)pt,        t1 = *(const float4*)(pt + IMG);
        d0 = make_float4(o0.x - t0.x, o0.y - t0.y, o0.z - t0.z, o0.w - t0.w);
        d1 = make_float4(o1.x - t1.x, o1.y - t1.y, o1.z - t1.z, o1.w - t1.w);
        dd.x = max4(o0.x, o0.y, o1.x, o1.y) - max4(t0.x, t0.y, t1.x, t1.y);
        dd.y = max4(o0.z, o0.w, o1.z, o1.w) - max4(t0.z, t0.w, t1.z, t1.w);
        if (edge_ld) {
            const float* poe = img_o + base + gx0 + 4;
            const float* pte = img_t + base + gx0 + 4;
            float2 a0 = *(const float2*)(poe + (size_t)ry0 * IMG);
            float2 a1 = *(const float2*)(poe + (size_t)(ry0 + 1) * IMG);
            float2 b0 = *(const float2*)(pte + (size_t)ry0 * IMG);
            float2 b1 = *(const float2*)(pte + (size_t)(ry0 + 1) * IMG);
            eR0  = a0.x - b0.x;
            eR1  = a1.x - b1.x;
            eddR = max4(a0.x, a0.y, a1.x, a1.y) - max4(b0.x, b0.y, b1.x, b1.y);
        }
    }

    float sa = 0.f, ca0 = 0.f, ca1 = 0.f, ca2 = 0.f, ba = 0.f;
    float sh = 0.f, ch0 = 0.f, ch1 = 0.f, bh = 0.f;
    float4 dprev = make_float4(0.f, 0.f, 0.f, 0.f);
    float2 ddprev = make_float2(0.f, 0.f);
    float pnd1 = 0.f, pnddx = 0.f;

    #pragma unroll 1
    for (int j = 0; j < NPAIR; j++) {
        const int gy0 = ry0 + 2 * j;
        const int gy1 = gy0 + 1;

        // ---- 1. prefetch raws for pair j+1 (consumed at step 4) ----
        float4 no0, no1, nt0, nt1;
        float2 ea0, ea1, eb0, eb1;
        {
            float4 z = make_float4(0.f, 0.f, 0.f, 0.f);
            float2 z2 = make_float2(0.f, 0.f);
            no0 = no1 = nt0 = nt1 = z;
            ea0 = ea1 = eb0 = eb1 = z2;
            if (j + 1 < NPAIR) {
                int ng = gy0 + 2;
                const float* po = po_base + (size_t)ng * IMG;
                const float* pt = pt_base + (size_t)ng * IMG;
                if (ng < IMG)     { no0 = *(const float4*)po;         nt0 = *(const float4*)pt; }
                if (ng + 1 < IMG) { no1 = *(const float4*)(po + IMG); nt1 = *(const float4*)(pt + IMG); }
                if (edge_ld) {
                    const float* poe = img_o + base + gx0 + 4;
                    const float* pte = img_t + base + gx0 + 4;
                    if (ng < IMG)     { ea0 = *(const float2*)(poe + (size_t)ng * IMG);
                                        eb0 = *(const float2*)(pte + (size_t)ng * IMG); }
                    if (ng + 1 < IMG) { ea1 = *(const float2*)(poe + (size_t)(ng + 1) * IMG);
                                        eb1 = *(const float2*)(pte + (size_t)(ng + 1) * IMG); }
                }
            }
        }

        // ---- 2. +1 neighbors via shuffle ----
        float t;
        t = __shfl_down_sync(0xFFFFFFFFu, d0.x, 1); float nd0  = isR ? eR0  : t;
        t = __shfl_down_sync(0xFFFFFFFFu, d1.x, 1); float nd1  = isR ? eR1  : t;
        t = __shfl_down_sync(0xFFFFFFFFu, dd.x, 1); float nddR = isR ? eddR : t;

        // ---- 3. FMA block (identical math to R6, split accumulators) ----
        // cross terms with previous pair (dprev = 0 at j=0 -> no-op)
        ca0 = fmaf(dprev.x, d0.x, ca0); ca0 = fmaf(dprev.y, d0.y, ca0);   // S
        ca0 = fmaf(dprev.z, d0.z, ca0); ca0 = fmaf(dprev.w, d0.w, ca0);
        ca1 = fmaf(dprev.x, d0.y, ca1); ca1 = fmaf(dprev.y, d0.z, ca1);   // SE
        ca1 = fmaf(dprev.z, d0.w, ca1); ca1 = fmaf(dprev.w, nd0,  ca1);
        ca2 = fmaf(dprev.y, d0.x, ca2); ca2 = fmaf(dprev.z, d0.y, ca2);   // SW
        ca2 = fmaf(dprev.w, d0.z, ca2); ca2 = fmaf(pnd1,    d0.w, ca2);

        ch0 = fmaf(ddprev.x, dd.x, ch0); ch0 = fmaf(ddprev.y, dd.y, ch0); // S
        ch1 = fmaf(ddprev.x, dd.y, ch1); ch1 = fmaf(ddprev.y, nddR, ch1); // SE
        ch0 = fmaf(ddprev.y, dd.x, ch0); ch0 = fmaf(pnddx,    dd.y, ch0); // SW

        if (j < NPAIR - 1) {
            sa = fmaf(d0.x, d0.x, sa); sa = fmaf(d0.y, d0.y, sa);
            sa = fmaf(d0.z, d0.z, sa); sa = fmaf(d0.w, d0.w, sa);
            sa = fmaf(d1.x, d1.x, sa); sa = fmaf(d1.y, d1.y, sa);
            sa = fmaf(d1.z, d1.z, sa); sa = fmaf(d1.w, d1.w, sa);

            ca0 = fmaf(d0.x, d0.y, ca0); ca0 = fmaf(d0.y, d0.z, ca0);    // E row0
            ca0 = fmaf(d0.z, d0.w, ca0); ca0 = fmaf(d0.w, nd0,  ca0);
            ca1 = fmaf(d1.x, d1.y, ca1); ca1 = fmaf(d1.y, d1.z, ca1);    // E row1
            ca1 = fmaf(d1.z, d1.w, ca1); ca1 = fmaf(d1.w, nd1,  ca1);
            ca2 = fmaf(d0.x, d1.x, ca2); ca2 = fmaf(d0.y, d1.y, ca2);    // S pair
            ca2 = fmaf(d0.z, d1.z, ca2); ca2 = fmaf(d0.w, d1.w, ca2);
            ca0 = fmaf(d0.x, d1.y, ca0); ca0 = fmaf(d0.y, d1.z, ca0);    // SE pair
            ca0 = fmaf(d0.z, d1.w, ca0); ca0 = fmaf(d0.w, nd1,  ca0);
            ca1 = fmaf(d0.y, d1.x, ca1); ca1 = fmaf(d0.z, d1.y, ca1);    // SW pair
            ca1 = fmaf(d0.w, d1.z, ca1); ca1 = fmaf(nd0,  d1.w, ca1);

            sh  = fmaf(dd.x, dd.x, sh);  sh  = fmaf(dd.y, dd.y, sh);
            ch1 = fmaf(dd.x, dd.y, ch1); ch1 = fmaf(dd.y, nddR, ch1);    // E half

            if (col_edge | (gy0 == 0) | (gy1 == IMG - 1)) {
                ba = fmaf(bw(gy0, gx0,     IMG) * d0.x, d0.x, ba);
                ba = fmaf(bw(gy0, gx0 + 1, IMG) * d0.y, d0.y, ba);
                ba = fmaf(bw(gy0, gx0 + 2, IMG) * d0.z, d0.z, ba);
                ba = fmaf(bw(gy0, gx0 + 3, IMG) * d0.w, d0.w, ba);
                ba = fmaf(bw(gy1, gx0,     IMG) * d1.x, d1.x, ba);
                ba = fmaf(bw(gy1, gx0 + 1, IMG) * d1.y, d1.y, ba);
                ba = fmaf(bw(gy1, gx0 + 2, IMG) * d1.z, d1.z, ba);
                ba = fmaf(bw(gy1, gx0 + 3, IMG) * d1.w, d1.w, ba);
            }
            int hgy = (ry0 >> 1) + j;
            if (col_edge | (hgy == 0) | (hgy == HIMG - 1)) {
                bh = fmaf(bw(hgy, hx0,     HIMG) * dd.x, dd.x, bh);
                bh = fmaf(bw(hgy, hx0 + 1, HIMG) * dd.y, dd.y, bh);
            }
        }

        // ---- 4. convert prefetched raws -> next pair diffs ----
        float4 pd0 = make_float4(no0.x - nt0.x, no0.y - nt0.y, no0.z - nt0.z, no0.w - nt0.w);
        float4 pd1 = make_float4(no1.x - nt1.x, no1.y - nt1.y, no1.z - nt1.z, no1.w - nt1.w);
        float2 pdd;
        pdd.x = max4(no0.x, no0.y, no1.x, no1.y) - max4(nt0.x, nt0.y, nt1.x, nt1.y);
        pdd.y = max4(no0.z, no0.w, no1.z, no1.w) - max4(nt0.z, nt0.w, nt1.z, nt1.w);
        float peR0  = ea0.x - eb0.x;
        float peR1  = ea1.x - eb1.x;
        float peddR = max4(ea0.x, ea0.y, ea1.x, ea1.y) - max4(eb0.x, eb0.y, eb1.x, eb1.y);

        // ---- 5. rotate ----
        dprev = d1; ddprev = dd; pnd1 = nd1; pnddx = nddR;
        d0 = pd0; d1 = pd1; dd = pdd;
        eR0 = peR0; eR1 = peR1; eddR = peddR;
    }

    // ---------------- block reduction + last-block finalize ----------------
    __shared__ float red[4];
    __shared__ unsigned int s_last;
    float ca = ca0 + ca1 + ca2;
    float ch = ch0 + ch1;
    float val = (24.f * sa - ba - 4.f * ca) * WG
              + (16.f * sh - bh - 4.f * ch) * WGD;
    #pragma unroll
    for (int off = 16; off; off >>= 1)
        val += __shfl_down_sync(0xFFFFFFFFu, val, off);
    int warp = tid >> 5;
    if (lane == 0) red[warp] = val;
    __syncthreads();
    if (tid == 0) {
        float s = red[0] + red[1] + red[2] + red[3];
        int bid = (blockIdx.z * GRIDY + blockIdx.y) * 2 + blockIdx.x;
        g_part[bid] = s;
        __threadfence();
        unsigned old = atomicAdd(&g_count, 1u);
        s_last = (old == NBLK - 1) ? 1u : 0u;
    }
    __syncthreads();

    if (s_last) {
        double s = 0.0;
        #pragma unroll
        for (int i = tid; i < NBLK; i += 128)
            s += (double)g_part[i];
        #pragma unroll
        for (int off = 16; off; off >>= 1)
            s += __shfl_down_sync(0xFFFFFFFFu, s, off);
        __shared__ double dred[4];
        if (lane == 0) dred[warp] = s;
        __syncthreads();
        if (tid == 0) {
            out[0] = (float)(dred[0] + dred[1] + dred[2] + dred[3]);
            g_count = 0;   // reset for next graph replay
        }
    }
}

extern "C" void kernel_launch(void* const* d_in, const int* in_sizes, int n_in,
                              void* d_out, int out_size) {
    const float* img_o = (const float*)d_in[0];
    const float* img_t = (const float*)d_in[1];
    dim3 grid(2, GRIDY, NIMG);
    gloss_corr<<<grid, 128>>>(img_o, img_t, (float*)d_out);
}